// round 7
// baseline (speedup 1.0000x reference)
#include <cuda_runtime.h>
#include <math.h>
#include <limits.h>
#include <stdint.h>

#define NN 50000
#define NP 50048          // NN padded to multiple of 128
#define FF 128
#define CC 512
#define EE 800000
#define HH 256

#define OFF_NEWX 0
#define OFF_ADJ  (CC*FF)
#define OFF_BATCH (OFF_ADJ + CC*CC)
#define OFF_S    (OFF_BATCH + CC)

// ---------------- device scratch (static, no allocations) ----------------
static __device__ float g_h[(size_t)NP*CC];     // GEMM outputs (padded rows)
static __device__ float g_Ah[(size_t)NP*HH];    // tf32-hi aggregated features (padded)
static __device__ float g_Al[(size_t)NP*HH];    // tf32-lo aggregated features (padded)
static __device__ float g_Wth[(size_t)CC*HH];   // transposed tf32-hi weights [Kout][Min]
static __device__ float g_Wtl[(size_t)CC*HH];   // transposed tf32-lo weights
static __device__ int   g_rowptr[NN+1];
static __device__ int   g_deg[NN];
static __device__ int   g_cursor[NN];
static __device__ int   g_csrsrc[EE];
static __device__ float g_inv[NN];
static __device__ float g_hs[NN];
static __device__ float g_invs[NN];
static __device__ float g_score[NN];
static __device__ int   g_cluster[NN];
static __device__ int   g_segkey[CC];
static __device__ int   g_segidx[CC];
static __device__ int   g_cintra[CC];
static __device__ int   g_part[256];

// ---------------- helpers ----------------
__device__ __forceinline__ int fenc(float f){ int i=__float_as_int(f); return i<0 ? (i^0x7FFFFFFF) : i; }
__device__ __forceinline__ float fdec(int i){ return __int_as_float(i<0 ? (i^0x7FFFFFFF) : i); }

__device__ __forceinline__ float to_tf32(float a){
  float r; asm("cvt.rna.tf32.f32 %0,%1;":"=f"(r):"f"(a)); return r;
}

__device__ __forceinline__ uint32_t smem_u32(const void* p){
  uint32_t a; asm("{ .reg .u64 t; cvta.to.shared.u64 t, %1; cvt.u32.u64 %0, t; }":"=r"(a):"l"(p)); return a;
}

__device__ __forceinline__ void cpa16f(uint32_t s, const void* g){
  asm volatile("cp.async.ca.shared.global [%0], [%1], 16;"::"r"(s),"l"(g));
}
#define CPA_COMMIT() asm volatile("cp.async.commit_group;")
#define CPA_WAIT1()  asm volatile("cp.async.wait_group 1;":::"memory")
#define CPA_WAIT0()  asm volatile("cp.async.wait_group 0;":::"memory")

// mma.sync m16n8k8 tf32: D += A*B (row.col), accumulate in place
__device__ __forceinline__ void mma8(float* c, const uint32_t* a, uint32_t b0, uint32_t b1){
  asm volatile(
    "mma.sync.aligned.m16n8k8.row.col.f32.tf32.tf32.f32 "
    "{%0,%1,%2,%3},{%4,%5,%6,%7},{%8,%9},{%0,%1,%2,%3};"
    : "+f"(c[0]),"+f"(c[1]),"+f"(c[2]),"+f"(c[3])
    : "r"(a[0]),"r"(a[1]),"r"(a[2]),"r"(a[3]),"r"(b0),"r"(b1));
}

// ---------------- setup kernels ----------------
__global__ void k_init(){
  int i=blockIdx.x*blockDim.x+threadIdx.x;
  if(i<NN) g_deg[i]=0;
  if(i<CC){ g_cintra[i]=0; g_segkey[i]=INT_MIN; g_segidx[i]=NN; }
}

__global__ void k_deg(const int* __restrict__ dst){
  int e=blockIdx.x*blockDim.x+threadIdx.x;
  if(e<EE) atomicAdd(&g_deg[dst[e]],1);
}

// 3-phase exclusive scan of g_deg -> g_rowptr
__global__ void k_scan1(){
  int b=blockIdx.x, t=threadIdx.x, i=b*256+t;
  int v=(i<NN)?g_deg[i]:0;
  int x=v;
  #pragma unroll
  for(int off=1;off<32;off<<=1){
    int y=__shfl_up_sync(0xffffffffu,x,off);
    if((t&31)>=off) x+=y;
  }
  __shared__ int ws[8];
  if((t&31)==31) ws[t>>5]=x;
  __syncthreads();
  if(t==0){ int s=0; for(int j=0;j<8;j++){int tmp=ws[j]; ws[j]=s; s+=tmp;} g_part[b]=s; }
  __syncthreads();
  if(i<NN) g_rowptr[i]= x - v + ws[t>>5];
}
__global__ void k_scan2(int nblk){
  int t=threadIdx.x;
  __shared__ int sh[256];
  sh[t]=(t<nblk)?g_part[t]:0;
  __syncthreads();
  if(t==0){ int s=0; for(int j=0;j<nblk;j++){int tmp=sh[j]; sh[j]=s; s+=tmp;} g_rowptr[NN]=s; }
  __syncthreads();
  if(t<nblk) g_part[t]=sh[t];
}
// fused: finalize rowptr + cursor + inv
__global__ void k_scan3p(){
  int i=blockIdx.x*blockDim.x+threadIdx.x;
  if(i>=NN) return;
  int v=g_rowptr[i]+g_part[i>>8];
  g_rowptr[i]=v;
  g_cursor[i]=v;
  g_inv[i]=rsqrtf((float)g_deg[i]+1.0f);
}

__global__ void k_scatter(const int* __restrict__ src, const int* __restrict__ dst){
  int e=blockIdx.x*blockDim.x+threadIdx.x;
  if(e>=EE) return;
  int d=dst[e];
  int p=atomicAdd(&g_cursor[d],1);
  g_csrsrc[p]=src[e];
}

// ---------------- aggregation with fused inv scaling + tf32 split ----------------
// agg[i] = inv_i*(inv_i*h[i] + sum_{e:dst=i} inv_src*h[src]); hi/lo tf32 split output
template<int V>
__global__ void k_agg(const float* __restrict__ h, float* __restrict__ ah, float* __restrict__ al){
  int warp=blockIdx.x*(blockDim.x>>5) + (threadIdx.x>>5);
  int lane=threadIdx.x&31;
  if(warp>=NN) return;
  const float4* h4=(const float4*)h;
  size_t base=(size_t)warp*(32*V);
  float wi=g_inv[warp];
  float4 acc[V];
  #pragma unroll
  for(int v=0;v<V;v++){
    float4 q=h4[base+v*32+lane];
    acc[v].x=q.x*wi; acc[v].y=q.y*wi; acc[v].z=q.z*wi; acc[v].w=q.w*wi;
  }
  int s=g_rowptr[warp], e=g_rowptr[warp+1];
  for(int t=s;t<e;t++){
    int src=g_csrsrc[t];
    float ws=g_inv[src];
    const float4* r=h4+(size_t)src*(32*V);
    #pragma unroll
    for(int v=0;v<V;v++){
      float4 q=r[v*32+lane];
      acc[v].x=fmaf(q.x,ws,acc[v].x);
      acc[v].y=fmaf(q.y,ws,acc[v].y);
      acc[v].z=fmaf(q.z,ws,acc[v].z);
      acc[v].w=fmaf(q.w,ws,acc[v].w);
    }
  }
  float4* ah4=(float4*)ah; float4* al4=(float4*)al;
  #pragma unroll
  for(int v=0;v<V;v++){
    float f[4]={acc[v].x*wi, acc[v].y*wi, acc[v].z*wi, acc[v].w*wi};
    float4 hi,lo;
    hi.x=to_tf32(f[0]); lo.x=to_tf32(f[0]-hi.x);
    hi.y=to_tf32(f[1]); lo.y=to_tf32(f[1]-hi.y);
    hi.z=to_tf32(f[2]); lo.z=to_tf32(f[2]-hi.z);
    hi.w=to_tf32(f[3]); lo.w=to_tf32(f[3]-hi.w);
    ah4[base+v*32+lane]=hi;
    al4[base+v*32+lane]=lo;
  }
}

// transpose + split W[Min][Kout] -> Wt_hi/Wt_lo [Kout][Min]
__global__ void k_wsplit(const float* __restrict__ W, int Min, int Kout){
  int idx=blockIdx.x*blockDim.x+threadIdx.x;
  if(idx>=Min*Kout) return;
  int m=idx/Kout, nk=idx-m*Kout;
  float w=W[idx];
  float hi=to_tf32(w);
  float lo=to_tf32(w-hi);
  g_Wth[(size_t)nk*Min+m]=hi;
  g_Wtl[(size_t)nk*Min+m]=lo;
}

// ---------------- tf32 split-3 mma.sync GEMM, double-buffered cp.async ----------------
// CTA tile 128(m) x 128(n); 8 warps 4m x 2n; warp tile 32x64; K chunks of 32; 2-stage pipe.
#define PAD 36
#define CHF (128*PAD)          // floats per matrix slab
#define CHB (CHF*4)            // bytes per matrix slab
__global__ __launch_bounds__(256,1) void k_mma(
    const float* __restrict__ Ah, const float* __restrict__ Al,
    const float* __restrict__ Bh, const float* __restrict__ Bl,
    const float* __restrict__ bias, float* __restrict__ C,
    int Min, int Kout)
{
  extern __shared__ float sm[];
  int tid=threadIdx.x, lane=tid&31, wid=tid>>5;
  int wm = wid&3, wn = wid>>2;         // 4x2 warp grid
  int bm = blockIdx.y*128, bn = blockIdx.x*128;

  float acc[2][8][4];
  #pragma unroll
  for(int a=0;a<2;a++)
    #pragma unroll
    for(int b=0;b<8;b++)
      #pragma unroll
      for(int c=0;c<4;c++) acc[a][b][c]=0.f;

  int r_ld = tid>>3, c_ld=(tid&7)*4;   // per-thread load coords (4 iterations of +32 rows)
  uint32_t s_base = smem_u32(sm);

  // issue loads for chunk ch into buffer b
  auto issue=[&](int ch, int b){
    int k0=ch<<5;
    uint32_t s0 = s_base + (uint32_t)b*4*CHB;
    #pragma unroll
    for(int it=0;it<4;it++){
      int r = r_ld + it*32;
      uint32_t soff=(uint32_t)(r*PAD+c_ld)*4;
      cpa16f(s0 +        soff, &Ah[(size_t)(bm+r)*Min+k0+c_ld]);
      cpa16f(s0 + CHB  + soff, &Al[(size_t)(bm+r)*Min+k0+c_ld]);
      cpa16f(s0 + 2*CHB+ soff, &Bh[(size_t)(bn+r)*Min+k0+c_ld]);
      cpa16f(s0 + 3*CHB+ soff, &Bl[(size_t)(bn+r)*Min+k0+c_ld]);
    }
    CPA_COMMIT();
  };

  int nch = Min>>5;
  issue(0,0);
  for(int ch=0; ch<nch; ch++){
    int b=ch&1;
    if(ch+1<nch){ issue(ch+1, b^1); CPA_WAIT1(); }
    else        { CPA_WAIT0(); }
    __syncthreads();

    const float* As_h = sm + b*4*CHF;
    const float* As_l = As_h + CHF;
    const float* Bs_h = As_l + CHF;
    const float* Bs_l = Bs_h + CHF;

    #pragma unroll
    for(int ks=0;ks<4;ks++){
      int kk=ks*8;
      uint32_t afh[2][4], afl[2][4];
      int ar = wm*32 + (lane>>2), ac = kk + (lane&3);
      #pragma unroll
      for(int mf=0;mf<2;mf++){
        int r0 = ar + mf*16;
        afh[mf][0]=__float_as_uint(As_h[r0*PAD+ac]);
        afh[mf][1]=__float_as_uint(As_h[(r0+8)*PAD+ac]);
        afh[mf][2]=__float_as_uint(As_h[r0*PAD+ac+4]);
        afh[mf][3]=__float_as_uint(As_h[(r0+8)*PAD+ac+4]);
        afl[mf][0]=__float_as_uint(As_l[r0*PAD+ac]);
        afl[mf][1]=__float_as_uint(As_l[(r0+8)*PAD+ac]);
        afl[mf][2]=__float_as_uint(As_l[r0*PAD+ac+4]);
        afl[mf][3]=__float_as_uint(As_l[(r0+8)*PAD+ac+4]);
      }
      #pragma unroll
      for(int nf=0;nf<8;nf++){
        int bn_r = wn*64 + nf*8 + (lane>>2);
        int bk = kk + (lane&3);
        uint32_t bh0=__float_as_uint(Bs_h[bn_r*PAD+bk]);
        uint32_t bh1=__float_as_uint(Bs_h[bn_r*PAD+bk+4]);
        uint32_t bl0=__float_as_uint(Bs_l[bn_r*PAD+bk]);
        uint32_t bl1=__float_as_uint(Bs_l[bn_r*PAD+bk+4]);
        #pragma unroll
        for(int mf=0;mf<2;mf++){
          mma8(acc[mf][nf], afh[mf], bh0, bh1);
          mma8(acc[mf][nf], afh[mf], bl0, bl1);
          mma8(acc[mf][nf], afl[mf], bh0, bh1);
        }
      }
    }
    __syncthreads();
  }

  // epilogue: bias + relu, unconditional float2 stores (C is row-padded)
  #pragma unroll
  for(int mf=0;mf<2;mf++){
    int row0 = bm + wm*32 + mf*16 + (lane>>2);
    #pragma unroll
    for(int nf=0;nf<8;nf++){
      int col = bn + wn*64 + nf*8 + (lane&3)*2;
      float b0v=bias[col], b1v=bias[col+1];
      float2 v0; v0.x=fmaxf(acc[mf][nf][0]+b0v,0.f); v0.y=fmaxf(acc[mf][nf][1]+b1v,0.f);
      *(float2*)&C[(size_t)row0*Kout+col]=v0;
      float2 v1; v1.x=fmaxf(acc[mf][nf][2]+b0v,0.f); v1.y=fmaxf(acc[mf][nf][3]+b1v,0.f);
      *(float2*)&C[(size_t)(row0+8)*Kout+col]=v1;
    }
  }
}
#define MMA_SMEM (2*4*CHB)

// ---------------- softmax + argmax (warp per row of 512) ----------------
__global__ void k_softmax(const float* __restrict__ h, float* __restrict__ S){
  int warp=blockIdx.x*(blockDim.x>>5)+(threadIdx.x>>5);
  int lane=threadIdx.x&31;
  if(warp>=NN) return;
  const float* row=h+(size_t)warp*CC;
  float vals[16];
  float m=-3.4e38f; int am=0;
  #pragma unroll
  for(int c=0;c<16;c++){
    float v=row[c*32+lane];
    vals[c]=v;
    if(v>m){m=v;am=c*32+lane;}
  }
  #pragma unroll
  for(int off=16;off>0;off>>=1){
    float om=__shfl_down_sync(0xffffffffu,m,off);
    int   oa=__shfl_down_sync(0xffffffffu,am,off);
    if(om>m || (om==m && oa<am)){m=om;am=oa;}
  }
  m=__shfl_sync(0xffffffffu,m,0);
  am=__shfl_sync(0xffffffffu,am,0);
  float s=0.f;
  #pragma unroll
  for(int c=0;c<16;c++){ vals[c]=expf(vals[c]-m); s+=vals[c]; }
  #pragma unroll
  for(int off=16;off>0;off>>=1) s+=__shfl_down_sync(0xffffffffu,s,off);
  s=__shfl_sync(0xffffffffu,s,0);
  float invs=1.f/s;
  float* so=S+(size_t)warp*CC;
  #pragma unroll
  for(int c=0;c<16;c++) so[c*32+lane]=vals[c]*invs;
  if(lane==0) g_cluster[warp]=am;
}

// ---------------- score branch ----------------
__global__ void k_hs(const float* __restrict__ x, const float* __restrict__ Wsm){
  int warp=blockIdx.x*(blockDim.x>>5)+(threadIdx.x>>5);
  int lane=threadIdx.x&31;
  if(warp>=NN) return;
  float4 v=((const float4*)x)[(size_t)warp*32+lane];
  float4 w=((const float4*)Wsm)[lane];
  float d=v.x*w.x+v.y*w.y+v.z*w.z+v.w*w.w;
  #pragma unroll
  for(int off=16;off>0;off>>=1) d+=__shfl_down_sync(0xffffffffu,d,off);
  if(lane==0) g_hs[warp]=d;
}

__global__ void k_degs(){
  int i=blockIdx.x*blockDim.x+threadIdx.x;
  if(i>=NN) return;
  int ci=g_cluster[i];
  int s=g_rowptr[i], e=g_rowptr[i+1], cnt=0;
  for(int t=s;t<e;t++) cnt += (g_cluster[g_csrsrc[t]]==ci) ? 1 : 0;
  g_invs[i]=rsqrtf((float)cnt+1.0f);
  if(cnt>0) atomicAdd(&g_cintra[ci],cnt);
}

__global__ void k_score(const float* __restrict__ bs){
  int i=blockIdx.x*blockDim.x+threadIdx.x;
  if(i>=NN) return;
  int ci=g_cluster[i];
  int s=g_rowptr[i], e=g_rowptr[i+1];
  float sum=0.f;
  for(int t=s;t<e;t++){
    int sn=g_csrsrc[t];
    if(g_cluster[sn]==ci) sum += g_invs[sn]*g_hs[sn];
  }
  float w=g_invs[i];
  g_score[i]=tanhf(w*(sum + w*g_hs[i]) + bs[0]);
}

__global__ void k_segmax(){
  int i=blockIdx.x*blockDim.x+threadIdx.x;
  if(i<NN) atomicMax(&g_segkey[g_cluster[i]], fenc(g_score[i]));
}

__global__ void k_argnode(){
  int i=blockIdx.x*blockDim.x+threadIdx.x;
  if(i>=NN) return;
  int c=g_cluster[i];
  if(fenc(g_score[i]) >= g_segkey[c]) atomicMin(&g_segidx[c], i);
}

// ---------------- outputs ----------------
__global__ void k_newx(const float* __restrict__ x, float* __restrict__ out){
  int c=blockIdx.x;
  int t=threadIdx.x;
  __shared__ float alpha; __shared__ int idx;
  if(t==0){
    alpha = (g_cintra[c]>0) ? fdec(g_segkey[c]) : 0.f;
    idx = min(g_segidx[c], NN-1);
  }
  __syncthreads();
  out[OFF_NEWX + c*FF + t] = x[(size_t)idx*FF + t]*alpha;
}

__global__ void k_adjzero(float* __restrict__ out){
  int i=blockIdx.x*blockDim.x+threadIdx.x;
  if(i<CC*CC+CC) out[OFF_ADJ+i]=0.f;
}

__global__ void k_adjfill(const int* __restrict__ src, const int* __restrict__ dst, float* __restrict__ out){
  int e=blockIdx.x*blockDim.x+threadIdx.x;
  if(e>=EE) return;
  int ci=g_cluster[src[e]], cj=g_cluster[dst[e]];
  if(ci!=cj && g_cintra[ci]>0 && g_cintra[cj]>0)
    out[OFF_ADJ + ci*CC + cj]=1.0f;
}

// ---------------- launch ----------------
extern "C" void kernel_launch(void* const* d_in, const int* in_sizes, int n_in,
                              void* d_out, int out_size)
{
  const float* x  =(const float*)d_in[0];
  const int*   ei =(const int*)  d_in[1];
  const float* W1 =(const float*)d_in[3];
  const float* b1 =(const float*)d_in[4];
  const float* W2 =(const float*)d_in[5];
  const float* b2 =(const float*)d_in[6];
  const float* W3 =(const float*)d_in[7];
  const float* b3 =(const float*)d_in[8];
  const float* Wsm=(const float*)d_in[9];
  const float* bs =(const float*)d_in[10];
  float* out=(float*)d_out;

  const int* srcp=ei;
  const int* dstp=ei+EE;

  float *p_h,*p_ah,*p_al,*p_wh,*p_wl;
  cudaGetSymbolAddress((void**)&p_h,  g_h);
  cudaGetSymbolAddress((void**)&p_ah, g_Ah);
  cudaGetSymbolAddress((void**)&p_al, g_Al);
  cudaGetSymbolAddress((void**)&p_wh, g_Wth);
  cudaGetSymbolAddress((void**)&p_wl, g_Wtl);

  cudaFuncSetAttribute(k_mma, cudaFuncAttributeMaxDynamicSharedMemorySize, MMA_SMEM);

  const int TB=256;
  const int gN=(NN+TB-1)/TB;       // 196
  const int gE=(EE+TB-1)/TB;
  const int gW=(NN+7)/8;
  const int gM=NP/128;             // 391

  // graph prep
  k_init<<<gN,TB>>>();
  k_deg<<<gE,TB>>>(dstp);
  k_scan1<<<gN,TB>>>();
  k_scan2<<<1,256>>>(gN);
  k_scan3p<<<gN,TB>>>();
  k_scatter<<<gE,TB>>>(srcp,dstp);

  // layer 1: F=128 -> 256
  k_wsplit<<<(128*256+TB-1)/TB,TB>>>(W1,128,256);
  k_agg<1><<<gW,TB>>>(x,p_ah,p_al);
  k_mma<<<dim3(2,gM),256,MMA_SMEM>>>(p_ah,p_al,p_wh,p_wl,b1,p_h,128,256);

  // layer 2: 256 -> 256
  k_wsplit<<<(256*256+TB-1)/TB,TB>>>(W2,256,256);
  k_agg<2><<<gW,TB>>>(p_h,p_ah,p_al);
  k_mma<<<dim3(2,gM),256,MMA_SMEM>>>(p_ah,p_al,p_wh,p_wl,b2,p_h,256,256);

  // layer 3: 256 -> 512
  k_wsplit<<<(256*512+TB-1)/TB,TB>>>(W3,256,512);
  k_agg<2><<<gW,TB>>>(p_h,p_ah,p_al);
  k_mma<<<dim3(4,gM),256,MMA_SMEM>>>(p_ah,p_al,p_wh,p_wl,b3,p_h,256,512);

  // softmax S + hard cluster assignment
  k_softmax<<<gW,TB>>>(p_h, out+OFF_S);

  // score branch
  k_hs<<<gW,TB>>>(x,Wsm);
  k_degs<<<gN,TB>>>();
  k_score<<<gN,TB>>>(bs);
  k_segmax<<<gN,TB>>>();
  k_argnode<<<gN,TB>>>();

  // outputs
  k_newx<<<CC,FF>>>(x,out);
  k_adjzero<<<(CC*CC+CC+TB-1)/TB,TB>>>(out);
  k_adjfill<<<gE,TB>>>(srcp,dstp,out);
}

// round 8
// speedup vs baseline: 1.0603x; 1.0603x over previous
#include <cuda_runtime.h>
#include <math.h>
#include <limits.h>
#include <stdint.h>

#define NN 50000
#define NP 50048          // NN padded to multiple of 128
#define FF 128
#define CC 512
#define EE 800000
#define HH 256

#define OFF_NEWX 0
#define OFF_ADJ  (CC*FF)
#define OFF_BATCH (OFF_ADJ + CC*CC)
#define OFF_S    (OFF_BATCH + CC)

// ---------------- device scratch (static, no allocations) ----------------
static __device__ float g_h[(size_t)NP*CC];     // GEMM outputs (padded rows)
static __device__ float g_Ah[(size_t)NP*HH];    // tf32-hi aggregated features (padded)
static __device__ float g_Al[(size_t)NP*HH];    // tf32-lo aggregated features (padded)
static __device__ float g_Wth[(size_t)CC*HH];   // transposed tf32-hi weights [Kout][Min]
static __device__ float g_Wtl[(size_t)CC*HH];   // transposed tf32-lo weights
static __device__ int   g_rowptr[NN+1];
static __device__ int   g_deg[NN];
static __device__ int   g_cursor[NN];
static __device__ int   g_csrsrc[EE];
static __device__ float g_inv[NN];
static __device__ float g_hs[NN];
static __device__ float g_invs[NN];
static __device__ float g_score[NN];
static __device__ int   g_cluster[NN];
static __device__ int   g_segkey[CC];
static __device__ int   g_segidx[CC];
static __device__ int   g_cintra[CC];
static __device__ int   g_part[256];

// ---------------- helpers ----------------
__device__ __forceinline__ int fenc(float f){ int i=__float_as_int(f); return i<0 ? (i^0x7FFFFFFF) : i; }
__device__ __forceinline__ float fdec(int i){ return __int_as_float(i<0 ? (i^0x7FFFFFFF) : i); }

__device__ __forceinline__ float to_tf32(float a){
  float r; asm("cvt.rna.tf32.f32 %0,%1;":"=f"(r):"f"(a)); return r;
}

__device__ __forceinline__ uint32_t smem_u32(const void* p){
  uint32_t a; asm("{ .reg .u64 t; cvta.to.shared.u64 t, %1; cvt.u32.u64 %0, t; }":"=r"(a):"l"(p)); return a;
}

__device__ __forceinline__ void cpa16f(uint32_t s, const void* g){
  asm volatile("cp.async.ca.shared.global [%0], [%1], 16;"::"r"(s),"l"(g));
}
#define CPA_COMMIT() asm volatile("cp.async.commit_group;")
#define CPA_WAIT0()  asm volatile("cp.async.wait_group 0;":::"memory")

// ldmatrix x4: each m8n8.b16 tile == 8x4 tf32 tile with exact mma fragment lane mapping
#define LDSM4(d, addr) asm volatile( \
    "ldmatrix.sync.aligned.m8n8.x4.shared.b16 {%0,%1,%2,%3},[%4];" \
    : "=r"((d)[0]),"=r"((d)[1]),"=r"((d)[2]),"=r"((d)[3]) : "r"(addr))

// mma.sync m16n8k8 tf32: D += A*B (row.col), accumulate in place
__device__ __forceinline__ void mma8(float* c, const uint32_t* a, uint32_t b0, uint32_t b1){
  asm volatile(
    "mma.sync.aligned.m16n8k8.row.col.f32.tf32.tf32.f32 "
    "{%0,%1,%2,%3},{%4,%5,%6,%7},{%8,%9},{%0,%1,%2,%3};"
    : "+f"(c[0]),"+f"(c[1]),"+f"(c[2]),"+f"(c[3])
    : "r"(a[0]),"r"(a[1]),"r"(a[2]),"r"(a[3]),"r"(b0),"r"(b1));
}

// ---------------- setup kernels ----------------
__global__ void k_init(){
  int i=blockIdx.x*blockDim.x+threadIdx.x;
  if(i<NN) g_deg[i]=0;
  if(i<CC){ g_cintra[i]=0; g_segkey[i]=INT_MIN; g_segidx[i]=NN; }
}

__global__ void k_deg(const int* __restrict__ dst){
  int e=blockIdx.x*blockDim.x+threadIdx.x;
  if(e<EE) atomicAdd(&g_deg[dst[e]],1);
}

// 3-phase exclusive scan of g_deg -> g_rowptr
__global__ void k_scan1(){
  int b=blockIdx.x, t=threadIdx.x, i=b*256+t;
  int v=(i<NN)?g_deg[i]:0;
  int x=v;
  #pragma unroll
  for(int off=1;off<32;off<<=1){
    int y=__shfl_up_sync(0xffffffffu,x,off);
    if((t&31)>=off) x+=y;
  }
  __shared__ int ws[8];
  if((t&31)==31) ws[t>>5]=x;
  __syncthreads();
  if(t==0){ int s=0; for(int j=0;j<8;j++){int tmp=ws[j]; ws[j]=s; s+=tmp;} g_part[b]=s; }
  __syncthreads();
  if(i<NN) g_rowptr[i]= x - v + ws[t>>5];
}
__global__ void k_scan2(int nblk){
  int t=threadIdx.x;
  __shared__ int sh[256];
  sh[t]=(t<nblk)?g_part[t]:0;
  __syncthreads();
  if(t==0){ int s=0; for(int j=0;j<nblk;j++){int tmp=sh[j]; sh[j]=s; s+=tmp;} g_rowptr[NN]=s; }
  __syncthreads();
  if(t<nblk) g_part[t]=sh[t];
}
// fused: finalize rowptr + cursor + inv
__global__ void k_scan3p(){
  int i=blockIdx.x*blockDim.x+threadIdx.x;
  if(i>=NN) return;
  int v=g_rowptr[i]+g_part[i>>8];
  g_rowptr[i]=v;
  g_cursor[i]=v;
  g_inv[i]=rsqrtf((float)g_deg[i]+1.0f);
}

__global__ void k_scatter(const int* __restrict__ src, const int* __restrict__ dst){
  int e=blockIdx.x*blockDim.x+threadIdx.x;
  if(e>=EE) return;
  int d=dst[e];
  int p=atomicAdd(&g_cursor[d],1);
  g_csrsrc[p]=src[e];
}

// ---------------- aggregation with fused inv scaling + tf32 split ----------------
// agg[i] = inv_i*(inv_i*h[i] + sum_{e:dst=i} inv_src*h[src]); hi/lo tf32 split output
template<int V>
__global__ void k_agg(const float* __restrict__ h, float* __restrict__ ah, float* __restrict__ al){
  int warp=blockIdx.x*(blockDim.x>>5) + (threadIdx.x>>5);
  int lane=threadIdx.x&31;
  if(warp>=NN) return;
  const float4* h4=(const float4*)h;
  size_t base=(size_t)warp*(32*V);
  float wi=g_inv[warp];
  float4 acc[V];
  #pragma unroll
  for(int v=0;v<V;v++){
    float4 q=h4[base+v*32+lane];
    acc[v].x=q.x*wi; acc[v].y=q.y*wi; acc[v].z=q.z*wi; acc[v].w=q.w*wi;
  }
  int s=g_rowptr[warp], e=g_rowptr[warp+1];
  for(int t=s;t<e;t++){
    int src=g_csrsrc[t];
    float ws=g_inv[src];
    const float4* r=h4+(size_t)src*(32*V);
    #pragma unroll
    for(int v=0;v<V;v++){
      float4 q=r[v*32+lane];
      acc[v].x=fmaf(q.x,ws,acc[v].x);
      acc[v].y=fmaf(q.y,ws,acc[v].y);
      acc[v].z=fmaf(q.z,ws,acc[v].z);
      acc[v].w=fmaf(q.w,ws,acc[v].w);
    }
  }
  float4* ah4=(float4*)ah; float4* al4=(float4*)al;
  #pragma unroll
  for(int v=0;v<V;v++){
    float f[4]={acc[v].x*wi, acc[v].y*wi, acc[v].z*wi, acc[v].w*wi};
    float4 hi,lo;
    hi.x=to_tf32(f[0]); lo.x=to_tf32(f[0]-hi.x);
    hi.y=to_tf32(f[1]); lo.y=to_tf32(f[1]-hi.y);
    hi.z=to_tf32(f[2]); lo.z=to_tf32(f[2]-hi.z);
    hi.w=to_tf32(f[3]); lo.w=to_tf32(f[3]-hi.w);
    ah4[base+v*32+lane]=hi;
    al4[base+v*32+lane]=lo;
  }
}

// transpose + split W[Min][Kout] -> Wt_hi/Wt_lo [Kout][Min]
__global__ void k_wsplit(const float* __restrict__ W, int Min, int Kout){
  int idx=blockIdx.x*blockDim.x+threadIdx.x;
  if(idx>=Min*Kout) return;
  int m=idx/Kout, nk=idx-m*Kout;
  float w=W[idx];
  float hi=to_tf32(w);
  float lo=to_tf32(w-hi);
  g_Wth[(size_t)nk*Min+m]=hi;
  g_Wtl[(size_t)nk*Min+m]=lo;
}

// ---------------- tf32 split-3 mma.sync GEMM with ldmatrix fragment loads ----------------
// CTA tile 128(m) x 128(n); 8 warps 4m x 2n; warp tile 32x64; K chunks of 32.
#define PAD 36
#define CHF (128*PAD)          // floats per matrix slab
#define CHB (CHF*4)            // bytes per matrix slab
__global__ __launch_bounds__(256,2) void k_mma(
    const float* __restrict__ Ah, const float* __restrict__ Al,
    const float* __restrict__ Bh, const float* __restrict__ Bl,
    const float* __restrict__ bias, float* __restrict__ C,
    int Min, int Kout)
{
  extern __shared__ float sm[];
  int tid=threadIdx.x, lane=tid&31, wid=tid>>5;
  int wm = wid&3, wn = wid>>2;         // 4x2 warp grid
  int bm = blockIdx.y*128, bn = blockIdx.x*128;

  uint32_t s_base = smem_u32(sm);
  uint32_t sAh=s_base, sAl=s_base+CHB, sBh=s_base+2*CHB, sBl=s_base+3*CHB;

  float acc[2][8][4];
  #pragma unroll
  for(int a=0;a<2;a++)
    #pragma unroll
    for(int b=0;b<8;b++)
      #pragma unroll
      for(int c=0;c<4;c++) acc[a][b][c]=0.f;

  // ldmatrix per-lane base offsets (bytes within a slab)
  int g=lane>>3, r=lane&7;
  uint32_t a_off[2], b_off[4];
  #pragma unroll
  for(int mf=0;mf<2;mf++)
    a_off[mf]=(uint32_t)((wm*32+mf*16+(g&1)*8+r)*PAD + (g>>1)*4)*4;
  #pragma unroll
  for(int p=0;p<4;p++)
    b_off[p]=(uint32_t)((wn*64+(2*p+(g>>1))*8+r)*PAD + (g&1)*4)*4;

  int r_ld = tid>>3, c_ld=(tid&7)*4;   // cp.async coords

  int nch = Min>>5;
  for(int ch=0; ch<nch; ch++){
    int k0=ch<<5;
    #pragma unroll
    for(int it=0;it<4;it++){
      int rr = r_ld + it*32;
      uint32_t soff=(uint32_t)(rr*PAD+c_ld)*4;
      cpa16f(sAh+soff, &Ah[(size_t)(bm+rr)*Min+k0+c_ld]);
      cpa16f(sAl+soff, &Al[(size_t)(bm+rr)*Min+k0+c_ld]);
      cpa16f(sBh+soff, &Bh[(size_t)(bn+rr)*Min+k0+c_ld]);
      cpa16f(sBl+soff, &Bl[(size_t)(bn+rr)*Min+k0+c_ld]);
    }
    CPA_COMMIT();
    CPA_WAIT0();
    __syncthreads();

    #pragma unroll
    for(int ks=0;ks<4;ks++){
      uint32_t ko = (uint32_t)ks*32;   // 8 floats
      uint32_t afh[2][4], afl[2][4];
      LDSM4(afh[0], sAh + a_off[0] + ko);
      LDSM4(afh[1], sAh + a_off[1] + ko);
      LDSM4(afl[0], sAl + a_off[0] + ko);
      LDSM4(afl[1], sAl + a_off[1] + ko);
      #pragma unroll
      for(int p=0;p<4;p++){
        uint32_t bh4[4], bl4[4];
        LDSM4(bh4, sBh + b_off[p] + ko);
        LDSM4(bl4, sBl + b_off[p] + ko);
        #pragma unroll
        for(int q=0;q<2;q++){
          int nf=2*p+q;
          uint32_t bh0=bh4[q*2], bh1=bh4[q*2+1];
          uint32_t bl0=bl4[q*2], bl1=bl4[q*2+1];
          #pragma unroll
          for(int mf=0;mf<2;mf++){
            mma8(acc[mf][nf], afh[mf], bh0, bh1);
            mma8(acc[mf][nf], afh[mf], bl0, bl1);
            mma8(acc[mf][nf], afl[mf], bh0, bh1);
          }
        }
      }
    }
    __syncthreads();
  }

  // epilogue: bias + relu, unconditional float2 stores (C is row-padded)
  #pragma unroll
  for(int mf=0;mf<2;mf++){
    int row0 = bm + wm*32 + mf*16 + (lane>>2);
    #pragma unroll
    for(int nf=0;nf<8;nf++){
      int col = bn + wn*64 + nf*8 + (lane&3)*2;
      float b0v=bias[col], b1v=bias[col+1];
      float2 v0; v0.x=fmaxf(acc[mf][nf][0]+b0v,0.f); v0.y=fmaxf(acc[mf][nf][1]+b1v,0.f);
      *(float2*)&C[(size_t)row0*Kout+col]=v0;
      float2 v1; v1.x=fmaxf(acc[mf][nf][2]+b0v,0.f); v1.y=fmaxf(acc[mf][nf][3]+b1v,0.f);
      *(float2*)&C[(size_t)(row0+8)*Kout+col]=v1;
    }
  }
}
#define MMA_SMEM (4*CHB)

// ---------------- softmax + argmax (warp per row of 512) ----------------
__global__ void k_softmax(const float* __restrict__ h, float* __restrict__ S){
  int warp=blockIdx.x*(blockDim.x>>5)+(threadIdx.x>>5);
  int lane=threadIdx.x&31;
  if(warp>=NN) return;
  const float* row=h+(size_t)warp*CC;
  float vals[16];
  float m=-3.4e38f; int am=0;
  #pragma unroll
  for(int c=0;c<16;c++){
    float v=row[c*32+lane];
    vals[c]=v;
    if(v>m){m=v;am=c*32+lane;}
  }
  #pragma unroll
  for(int off=16;off>0;off>>=1){
    float om=__shfl_down_sync(0xffffffffu,m,off);
    int   oa=__shfl_down_sync(0xffffffffu,am,off);
    if(om>m || (om==m && oa<am)){m=om;am=oa;}
  }
  m=__shfl_sync(0xffffffffu,m,0);
  am=__shfl_sync(0xffffffffu,am,0);
  float s=0.f;
  #pragma unroll
  for(int c=0;c<16;c++){ vals[c]=expf(vals[c]-m); s+=vals[c]; }
  #pragma unroll
  for(int off=16;off>0;off>>=1) s+=__shfl_down_sync(0xffffffffu,s,off);
  s=__shfl_sync(0xffffffffu,s,0);
  float invs=1.f/s;
  float* so=S+(size_t)warp*CC;
  #pragma unroll
  for(int c=0;c<16;c++) so[c*32+lane]=vals[c]*invs;
  if(lane==0) g_cluster[warp]=am;
}

// ---------------- score branch ----------------
__global__ void k_hs(const float* __restrict__ x, const float* __restrict__ Wsm){
  int warp=blockIdx.x*(blockDim.x>>5)+(threadIdx.x>>5);
  int lane=threadIdx.x&31;
  if(warp>=NN) return;
  float4 v=((const float4*)x)[(size_t)warp*32+lane];
  float4 w=((const float4*)Wsm)[lane];
  float d=v.x*w.x+v.y*w.y+v.z*w.z+v.w*w.w;
  #pragma unroll
  for(int off=16;off>0;off>>=1) d+=__shfl_down_sync(0xffffffffu,d,off);
  if(lane==0) g_hs[warp]=d;
}

__global__ void k_degs(){
  int i=blockIdx.x*blockDim.x+threadIdx.x;
  if(i>=NN) return;
  int ci=g_cluster[i];
  int s=g_rowptr[i], e=g_rowptr[i+1], cnt=0;
  for(int t=s;t<e;t++) cnt += (g_cluster[g_csrsrc[t]]==ci) ? 1 : 0;
  g_invs[i]=rsqrtf((float)cnt+1.0f);
  if(cnt>0) atomicAdd(&g_cintra[ci],cnt);
}

__global__ void k_score(const float* __restrict__ bs){
  int i=blockIdx.x*blockDim.x+threadIdx.x;
  if(i>=NN) return;
  int ci=g_cluster[i];
  int s=g_rowptr[i], e=g_rowptr[i+1];
  float sum=0.f;
  for(int t=s;t<e;t++){
    int sn=g_csrsrc[t];
    if(g_cluster[sn]==ci) sum += g_invs[sn]*g_hs[sn];
  }
  float w=g_invs[i];
  g_score[i]=tanhf(w*(sum + w*g_hs[i]) + bs[0]);
}

__global__ void k_segmax(){
  int i=blockIdx.x*blockDim.x+threadIdx.x;
  if(i<NN) atomicMax(&g_segkey[g_cluster[i]], fenc(g_score[i]));
}

__global__ void k_argnode(){
  int i=blockIdx.x*blockDim.x+threadIdx.x;
  if(i>=NN) return;
  int c=g_cluster[i];
  if(fenc(g_score[i]) >= g_segkey[c]) atomicMin(&g_segidx[c], i);
}

// ---------------- outputs ----------------
__global__ void k_newx(const float* __restrict__ x, float* __restrict__ out){
  int c=blockIdx.x;
  int t=threadIdx.x;
  __shared__ float alpha; __shared__ int idx;
  if(t==0){
    alpha = (g_cintra[c]>0) ? fdec(g_segkey[c]) : 0.f;
    idx = min(g_segidx[c], NN-1);
  }
  __syncthreads();
  out[OFF_NEWX + c*FF + t] = x[(size_t)idx*FF + t]*alpha;
}

__global__ void k_adjzero(float* __restrict__ out){
  int i=blockIdx.x*blockDim.x+threadIdx.x;
  if(i<CC*CC+CC) out[OFF_ADJ+i]=0.f;
}

__global__ void k_adjfill(const int* __restrict__ src, const int* __restrict__ dst, float* __restrict__ out){
  int e=blockIdx.x*blockDim.x+threadIdx.x;
  if(e>=EE) return;
  int ci=g_cluster[src[e]], cj=g_cluster[dst[e]];
  if(ci!=cj && g_cintra[ci]>0 && g_cintra[cj]>0)
    out[OFF_ADJ + ci*CC + cj]=1.0f;
}

// ---------------- launch ----------------
extern "C" void kernel_launch(void* const* d_in, const int* in_sizes, int n_in,
                              void* d_out, int out_size)
{
  const float* x  =(const float*)d_in[0];
  const int*   ei =(const int*)  d_in[1];
  const float* W1 =(const float*)d_in[3];
  const float* b1 =(const float*)d_in[4];
  const float* W2 =(const float*)d_in[5];
  const float* b2 =(const float*)d_in[6];
  const float* W3 =(const float*)d_in[7];
  const float* b3 =(const float*)d_in[8];
  const float* Wsm=(const float*)d_in[9];
  const float* bs =(const float*)d_in[10];
  float* out=(float*)d_out;

  const int* srcp=ei;
  const int* dstp=ei+EE;

  float *p_h,*p_ah,*p_al,*p_wh,*p_wl;
  cudaGetSymbolAddress((void**)&p_h,  g_h);
  cudaGetSymbolAddress((void**)&p_ah, g_Ah);
  cudaGetSymbolAddress((void**)&p_al, g_Al);
  cudaGetSymbolAddress((void**)&p_wh, g_Wth);
  cudaGetSymbolAddress((void**)&p_wl, g_Wtl);

  cudaFuncSetAttribute(k_mma, cudaFuncAttributeMaxDynamicSharedMemorySize, MMA_SMEM);

  const int TB=256;
  const int gN=(NN+TB-1)/TB;       // 196
  const int gE=(EE+TB-1)/TB;
  const int gW=(NN+7)/8;
  const int gM=NP/128;             // 391

  // graph prep
  k_init<<<gN,TB>>>();
  k_deg<<<gE,TB>>>(dstp);
  k_scan1<<<gN,TB>>>();
  k_scan2<<<1,256>>>(gN);
  k_scan3p<<<gN,TB>>>();
  k_scatter<<<gE,TB>>>(srcp,dstp);

  // layer 1: F=128 -> 256
  k_wsplit<<<(128*256+TB-1)/TB,TB>>>(W1,128,256);
  k_agg<1><<<gW,TB>>>(x,p_ah,p_al);
  k_mma<<<dim3(2,gM),256,MMA_SMEM>>>(p_ah,p_al,p_wh,p_wl,b1,p_h,128,256);

  // layer 2: 256 -> 256
  k_wsplit<<<(256*256+TB-1)/TB,TB>>>(W2,256,256);
  k_agg<2><<<gW,TB>>>(p_h,p_ah,p_al);
  k_mma<<<dim3(2,gM),256,MMA_SMEM>>>(p_ah,p_al,p_wh,p_wl,b2,p_h,256,256);

  // layer 3: 256 -> 512
  k_wsplit<<<(256*512+TB-1)/TB,TB>>>(W3,256,512);
  k_agg<2><<<gW,TB>>>(p_h,p_ah,p_al);
  k_mma<<<dim3(4,gM),256,MMA_SMEM>>>(p_ah,p_al,p_wh,p_wl,b3,p_h,256,512);

  // softmax S + hard cluster assignment
  k_softmax<<<gW,TB>>>(p_h, out+OFF_S);

  // score branch
  k_hs<<<gW,TB>>>(x,Wsm);
  k_degs<<<gN,TB>>>();
  k_score<<<gN,TB>>>(bs);
  k_segmax<<<gN,TB>>>();
  k_argnode<<<gN,TB>>>();

  // outputs
  k_newx<<<CC,FF>>>(x,out);
  k_adjzero<<<(CC*CC+CC+TB-1)/TB,TB>>>(out);
  k_adjfill<<<gE,TB>>>(srcp,dstp,out);
}

// round 9
// speedup vs baseline: 1.0870x; 1.0252x over previous
#include <cuda_runtime.h>
#include <math.h>
#include <limits.h>
#include <stdint.h>

#define NN 50000
#define NP 50048          // NN padded to multiple of 128
#define FF 128
#define CC 512
#define EE 800000
#define HH 256

#define OFF_NEWX 0
#define OFF_ADJ  (CC*FF)
#define OFF_BATCH (OFF_ADJ + CC*CC)
#define OFF_S    (OFF_BATCH + CC)

// weight slab offsets (elements) in g_Wth/g_Wtl
#define WOFF1 0
#define WOFF2 (128*256)
#define WOFF3 (128*256+256*256)
#define WTOT  (128*256+256*256+256*512)

// ---------------- device scratch (static, no allocations) ----------------
static __device__ float g_h[(size_t)NP*CC];     // GEMM outputs (padded rows)
static __device__ float g_Ah[(size_t)NP*HH];    // tf32-hi aggregated features (padded)
static __device__ float g_Al[(size_t)NP*HH];    // tf32-lo aggregated features (padded)
static __device__ float g_Wth[WTOT];            // transposed tf32-hi weights (all layers)
static __device__ float g_Wtl[WTOT];            // transposed tf32-lo weights
static __device__ int   g_rowptr[NN+1];
static __device__ int   g_deg[NN];
static __device__ int   g_cursor[NN];
static __device__ int   g_csrsrc[EE];
static __device__ float g_inv[NN];
static __device__ float g_hs[NN];
static __device__ float g_invs[NN];
static __device__ int   g_cluster[NN];
static __device__ unsigned long long g_segpack[CC];
static __device__ int   g_cintra[CC];
static __device__ int   g_part[256];

// ---------------- helpers ----------------
__device__ __forceinline__ int fenc(float f){ int i=__float_as_int(f); return i<0 ? (i^0x7FFFFFFF) : i; }
__device__ __forceinline__ float fdec(int i){ return __int_as_float(i<0 ? (i^0x7FFFFFFF) : i); }

__device__ __forceinline__ float to_tf32(float a){
  float r; asm("cvt.rna.tf32.f32 %0,%1;":"=f"(r):"f"(a)); return r;
}

__device__ __forceinline__ uint32_t smem_u32(const void* p){
  uint32_t a; asm("{ .reg .u64 t; cvta.to.shared.u64 t, %1; cvt.u32.u64 %0, t; }":"=r"(a):"l"(p)); return a;
}

__device__ __forceinline__ void cpa16f(uint32_t s, const void* g){
  asm volatile("cp.async.ca.shared.global [%0], [%1], 16;"::"r"(s),"l"(g));
}
#define CPA_COMMIT() asm volatile("cp.async.commit_group;")
#define CPA_WAIT0()  asm volatile("cp.async.wait_group 0;":::"memory")

// ldmatrix x4: each m8n8.b16 tile == 8x4 tf32 tile with exact mma fragment lane mapping
#define LDSM4(d, addr) asm volatile( \
    "ldmatrix.sync.aligned.m8n8.x4.shared.b16 {%0,%1,%2,%3},[%4];" \
    : "=r"((d)[0]),"=r"((d)[1]),"=r"((d)[2]),"=r"((d)[3]) : "r"(addr))

// mma.sync m16n8k8 tf32: D += A*B (row.col), accumulate in place
__device__ __forceinline__ void mma8(float* c, const uint32_t* a, uint32_t b0, uint32_t b1){
  asm volatile(
    "mma.sync.aligned.m16n8k8.row.col.f32.tf32.tf32.f32 "
    "{%0,%1,%2,%3},{%4,%5,%6,%7},{%8,%9},{%0,%1,%2,%3};"
    : "+f"(c[0]),"+f"(c[1]),"+f"(c[2]),"+f"(c[3])
    : "r"(a[0]),"r"(a[1]),"r"(a[2]),"r"(a[3]),"r"(b0),"r"(b1));
}

// ---------------- setup kernels ----------------
// deg zero + cluster-state init + adj/batch zero (out region stable across the launch)
__global__ void k_init(float* __restrict__ out){
  int i=blockIdx.x*blockDim.x+threadIdx.x;
  if(i<NN) g_deg[i]=0;
  if(i<CC){ g_cintra[i]=0; g_segpack[i]=0ull; }
  if(i<CC*CC+CC) out[OFF_ADJ+i]=0.f;
}

__global__ void k_deg(const int* __restrict__ dst){
  int e=blockIdx.x*blockDim.x+threadIdx.x;
  if(e<EE) atomicAdd(&g_deg[dst[e]],1);
}

// 3-phase exclusive scan of g_deg -> g_rowptr
__global__ void k_scan1(){
  int b=blockIdx.x, t=threadIdx.x, i=b*256+t;
  int v=(i<NN)?g_deg[i]:0;
  int x=v;
  #pragma unroll
  for(int off=1;off<32;off<<=1){
    int y=__shfl_up_sync(0xffffffffu,x,off);
    if((t&31)>=off) x+=y;
  }
  __shared__ int ws[8];
  if((t&31)==31) ws[t>>5]=x;
  __syncthreads();
  if(t==0){ int s=0; for(int j=0;j<8;j++){int tmp=ws[j]; ws[j]=s; s+=tmp;} g_part[b]=s; }
  __syncthreads();
  if(i<NN) g_rowptr[i]= x - v + ws[t>>5];
}
__global__ void k_scan2(int nblk){
  int t=threadIdx.x;
  __shared__ int sh[256];
  sh[t]=(t<nblk)?g_part[t]:0;
  __syncthreads();
  if(t==0){ int s=0; for(int j=0;j<nblk;j++){int tmp=sh[j]; sh[j]=s; s+=tmp;} g_rowptr[NN]=s; }
  __syncthreads();
  if(t<nblk) g_part[t]=sh[t];
}
// fused: finalize rowptr + cursor + inv
__global__ void k_scan3p(){
  int i=blockIdx.x*blockDim.x+threadIdx.x;
  if(i>=NN) return;
  int v=g_rowptr[i]+g_part[i>>8];
  g_rowptr[i]=v;
  g_cursor[i]=v;
  g_inv[i]=rsqrtf((float)g_deg[i]+1.0f);
}

__global__ void k_scatter(const int* __restrict__ src, const int* __restrict__ dst){
  int e=blockIdx.x*blockDim.x+threadIdx.x;
  if(e>=EE) return;
  int d=dst[e];
  int p=atomicAdd(&g_cursor[d],1);
  g_csrsrc[p]=src[e];
}

// ---------------- aggregation with fused inv scaling + tf32 split (+ optional hs) ----------------
// agg[i] = inv_i*(inv_i*h[i] + sum_{e:dst=i} inv_src*h[src]); hi/lo tf32 split output
template<int V, bool HS>
__global__ void k_agg(const float* __restrict__ h, float* __restrict__ ah, float* __restrict__ al,
                      const float* __restrict__ Wsm){
  int warp=blockIdx.x*(blockDim.x>>5) + (threadIdx.x>>5);
  int lane=threadIdx.x&31;
  if(warp>=NN) return;
  const float4* h4=(const float4*)h;
  size_t base=(size_t)warp*(32*V);
  float wi=g_inv[warp];
  float4 acc[V];
  #pragma unroll
  for(int v=0;v<V;v++){
    float4 q=h4[base+v*32+lane];
    if(HS && v==0){
      float4 w=((const float4*)Wsm)[lane];
      float d=q.x*w.x+q.y*w.y+q.z*w.z+q.w*w.w;
      #pragma unroll
      for(int off=16;off>0;off>>=1) d+=__shfl_down_sync(0xffffffffu,d,off);
      if(lane==0) g_hs[warp]=d;
    }
    acc[v].x=q.x*wi; acc[v].y=q.y*wi; acc[v].z=q.z*wi; acc[v].w=q.w*wi;
  }
  int s=g_rowptr[warp], e=g_rowptr[warp+1];
  for(int t=s;t<e;t++){
    int src=g_csrsrc[t];
    float ws=g_inv[src];
    const float4* r=h4+(size_t)src*(32*V);
    #pragma unroll
    for(int v=0;v<V;v++){
      float4 q=r[v*32+lane];
      acc[v].x=fmaf(q.x,ws,acc[v].x);
      acc[v].y=fmaf(q.y,ws,acc[v].y);
      acc[v].z=fmaf(q.z,ws,acc[v].z);
      acc[v].w=fmaf(q.w,ws,acc[v].w);
    }
  }
  float4* ah4=(float4*)ah; float4* al4=(float4*)al;
  #pragma unroll
  for(int v=0;v<V;v++){
    float f[4]={acc[v].x*wi, acc[v].y*wi, acc[v].z*wi, acc[v].w*wi};
    float4 hi,lo;
    hi.x=to_tf32(f[0]); lo.x=to_tf32(f[0]-hi.x);
    hi.y=to_tf32(f[1]); lo.y=to_tf32(f[1]-hi.y);
    hi.z=to_tf32(f[2]); lo.z=to_tf32(f[2]-hi.z);
    hi.w=to_tf32(f[3]); lo.w=to_tf32(f[3]-hi.w);
    ah4[base+v*32+lane]=hi;
    al4[base+v*32+lane]=lo;
  }
}

// transpose + split all three weight matrices in one kernel
__global__ void k_wsplit3(const float* __restrict__ W1, const float* __restrict__ W2,
                          const float* __restrict__ W3){
  int idx=blockIdx.x*blockDim.x+threadIdx.x;
  if(idx>=WTOT) return;
  const float* W; int Min,Kout,off,li;
  if(idx<WOFF2){ W=W1; Min=128; Kout=256; off=WOFF1; li=idx; }
  else if(idx<WOFF3){ W=W2; Min=256; Kout=256; off=WOFF2; li=idx-WOFF2; }
  else { W=W3; Min=256; Kout=512; off=WOFF3; li=idx-WOFF3; }
  int m=li/Kout, nk=li-m*Kout;
  float w=W[li];
  float hi=to_tf32(w);
  float lo=to_tf32(w-hi);
  g_Wth[off+nk*Min+m]=hi;
  g_Wtl[off+nk*Min+m]=lo;
}

// ---------------- tf32 split-3 mma.sync GEMM with ldmatrix fragment loads ----------------
// CTA tile 128(m) x 128(n); 8 warps 4m x 2n; warp tile 32x64; K chunks of 32.
#define PAD 36
#define CHF (128*PAD)          // floats per matrix slab
#define CHB (CHF*4)            // bytes per matrix slab
__global__ __launch_bounds__(256,2) void k_mma(
    const float* __restrict__ Ah, const float* __restrict__ Al,
    const float* __restrict__ Bh, const float* __restrict__ Bl,
    const float* __restrict__ bias, float* __restrict__ C,
    int Min, int Kout)
{
  extern __shared__ float sm[];
  int tid=threadIdx.x, lane=tid&31, wid=tid>>5;
  int wm = wid&3, wn = wid>>2;         // 4x2 warp grid
  int bm = blockIdx.y*128, bn = blockIdx.x*128;

  uint32_t s_base = smem_u32(sm);
  uint32_t sAh=s_base, sAl=s_base+CHB, sBh=s_base+2*CHB, sBl=s_base+3*CHB;

  float acc[2][8][4];
  #pragma unroll
  for(int a=0;a<2;a++)
    #pragma unroll
    for(int b=0;b<8;b++)
      #pragma unroll
      for(int c=0;c<4;c++) acc[a][b][c]=0.f;

  // ldmatrix per-lane base offsets (bytes within a slab)
  int g=lane>>3, r=lane&7;
  uint32_t a_off[2], b_off[4];
  #pragma unroll
  for(int mf=0;mf<2;mf++)
    a_off[mf]=(uint32_t)((wm*32+mf*16+(g&1)*8+r)*PAD + (g>>1)*4)*4;
  #pragma unroll
  for(int p=0;p<4;p++)
    b_off[p]=(uint32_t)((wn*64+(2*p+(g>>1))*8+r)*PAD + (g&1)*4)*4;

  int r_ld = tid>>3, c_ld=(tid&7)*4;   // cp.async coords

  int nch = Min>>5;
  for(int ch=0; ch<nch; ch++){
    int k0=ch<<5;
    #pragma unroll
    for(int it=0;it<4;it++){
      int rr = r_ld + it*32;
      uint32_t soff=(uint32_t)(rr*PAD+c_ld)*4;
      cpa16f(sAh+soff, &Ah[(size_t)(bm+rr)*Min+k0+c_ld]);
      cpa16f(sAl+soff, &Al[(size_t)(bm+rr)*Min+k0+c_ld]);
      cpa16f(sBh+soff, &Bh[(size_t)(bn+rr)*Min+k0+c_ld]);
      cpa16f(sBl+soff, &Bl[(size_t)(bn+rr)*Min+k0+c_ld]);
    }
    CPA_COMMIT();
    CPA_WAIT0();
    __syncthreads();

    #pragma unroll
    for(int ks=0;ks<4;ks++){
      uint32_t ko = (uint32_t)ks*32;   // 8 floats
      uint32_t afh[2][4], afl[2][4];
      LDSM4(afh[0], sAh + a_off[0] + ko);
      LDSM4(afh[1], sAh + a_off[1] + ko);
      LDSM4(afl[0], sAl + a_off[0] + ko);
      LDSM4(afl[1], sAl + a_off[1] + ko);
      #pragma unroll
      for(int p=0;p<4;p++){
        uint32_t bh4[4], bl4[4];
        LDSM4(bh4, sBh + b_off[p] + ko);
        LDSM4(bl4, sBl + b_off[p] + ko);
        #pragma unroll
        for(int q=0;q<2;q++){
          int nf=2*p+q;
          uint32_t bh0=bh4[q*2], bh1=bh4[q*2+1];
          uint32_t bl0=bl4[q*2], bl1=bl4[q*2+1];
          #pragma unroll
          for(int mf=0;mf<2;mf++){
            mma8(acc[mf][nf], afh[mf], bh0, bh1);
            mma8(acc[mf][nf], afh[mf], bl0, bl1);
            mma8(acc[mf][nf], afl[mf], bh0, bh1);
          }
        }
      }
    }
    __syncthreads();
  }

  // epilogue: bias + relu, unconditional float2 stores (C is row-padded)
  #pragma unroll
  for(int mf=0;mf<2;mf++){
    int row0 = bm + wm*32 + mf*16 + (lane>>2);
    #pragma unroll
    for(int nf=0;nf<8;nf++){
      int col = bn + wn*64 + nf*8 + (lane&3)*2;
      float b0v=bias[col], b1v=bias[col+1];
      float2 v0; v0.x=fmaxf(acc[mf][nf][0]+b0v,0.f); v0.y=fmaxf(acc[mf][nf][1]+b1v,0.f);
      *(float2*)&C[(size_t)row0*Kout+col]=v0;
      float2 v1; v1.x=fmaxf(acc[mf][nf][2]+b0v,0.f); v1.y=fmaxf(acc[mf][nf][3]+b1v,0.f);
      *(float2*)&C[(size_t)(row0+8)*Kout+col]=v1;
    }
  }
}
#define MMA_SMEM (4*CHB)

// ---------------- softmax + argmax (warp per row of 512) ----------------
__global__ void k_softmax(const float* __restrict__ h, float* __restrict__ S){
  int warp=blockIdx.x*(blockDim.x>>5)+(threadIdx.x>>5);
  int lane=threadIdx.x&31;
  if(warp>=NN) return;
  const float* row=h+(size_t)warp*CC;
  float vals[16];
  float m=-3.4e38f; int am=0;
  #pragma unroll
  for(int c=0;c<16;c++){
    float v=row[c*32+lane];
    vals[c]=v;
    if(v>m){m=v;am=c*32+lane;}
  }
  #pragma unroll
  for(int off=16;off>0;off>>=1){
    float om=__shfl_down_sync(0xffffffffu,m,off);
    int   oa=__shfl_down_sync(0xffffffffu,am,off);
    if(om>m || (om==m && oa<am)){m=om;am=oa;}
  }
  m=__shfl_sync(0xffffffffu,m,0);
  am=__shfl_sync(0xffffffffu,am,0);
  float s=0.f;
  #pragma unroll
  for(int c=0;c<16;c++){ vals[c]=expf(vals[c]-m); s+=vals[c]; }
  #pragma unroll
  for(int off=16;off>0;off>>=1) s+=__shfl_down_sync(0xffffffffu,s,off);
  s=__shfl_sync(0xffffffffu,s,0);
  float invs=1.f/s;
  float* so=S+(size_t)warp*CC;
  #pragma unroll
  for(int c=0;c<16;c++) so[c*32+lane]=vals[c]*invs;
  if(lane==0) g_cluster[warp]=am;
}

// ---------------- score branch ----------------
__global__ void k_degs(){
  int i=blockIdx.x*blockDim.x+threadIdx.x;
  if(i>=NN) return;
  int ci=g_cluster[i];
  int s=g_rowptr[i], e=g_rowptr[i+1], cnt=0;
  for(int t=s;t<e;t++) cnt += (g_cluster[g_csrsrc[t]]==ci) ? 1 : 0;
  g_invs[i]=rsqrtf((float)cnt+1.0f);
  if(cnt>0) atomicAdd(&g_cintra[ci],cnt);
}

// score + packed segmax/argmin + coarse adjacency, all in one CSR pass
__global__ void k_score(const float* __restrict__ bs, float* __restrict__ out){
  int i=blockIdx.x*blockDim.x+threadIdx.x;
  if(i>=NN) return;
  int ci=g_cluster[i];
  bool iok = g_cintra[ci]>0;
  int s=g_rowptr[i], e=g_rowptr[i+1];
  float sum=0.f;
  for(int t=s;t<e;t++){
    int sn=g_csrsrc[t];
    int cs=g_cluster[sn];
    if(cs==ci) sum += g_invs[sn]*g_hs[sn];
    else if(iok && g_cintra[cs]>0) out[OFF_ADJ + cs*CC + ci]=1.0f;
  }
  float w=g_invs[i];
  float sc=tanhf(w*(sum + w*g_hs[i]) + bs[0]);
  unsigned int key=((unsigned int)fenc(sc))^0x80000000u;
  unsigned long long pack=((unsigned long long)key<<32)|(unsigned int)(NN-1-i);
  atomicMax(&g_segpack[ci], pack);
}

// ---------------- outputs ----------------
__global__ void k_newx(const float* __restrict__ x, float* __restrict__ out){
  int c=blockIdx.x;
  int t=threadIdx.x;
  __shared__ float alpha; __shared__ int idx;
  if(t==0){
    unsigned long long p=g_segpack[c];
    int sidx = NN-1-(int)(unsigned int)(p&0xffffffffu);
    idx = min(max(sidx,0), NN-1);
    float sc = fdec((int)((unsigned int)(p>>32)^0x80000000u));
    alpha = (g_cintra[c]>0) ? sc : 0.f;
  }
  __syncthreads();
  out[OFF_NEWX + c*FF + t] = x[(size_t)idx*FF + t]*alpha;
}

// ---------------- launch ----------------
extern "C" void kernel_launch(void* const* d_in, const int* in_sizes, int n_in,
                              void* d_out, int out_size)
{
  const float* x  =(const float*)d_in[0];
  const int*   ei =(const int*)  d_in[1];
  const float* W1 =(const float*)d_in[3];
  const float* b1 =(const float*)d_in[4];
  const float* W2 =(const float*)d_in[5];
  const float* b2 =(const float*)d_in[6];
  const float* W3 =(const float*)d_in[7];
  const float* b3 =(const float*)d_in[8];
  const float* Wsm=(const float*)d_in[9];
  const float* bs =(const float*)d_in[10];
  float* out=(float*)d_out;

  const int* srcp=ei;
  const int* dstp=ei+EE;

  float *p_h,*p_ah,*p_al,*p_wh,*p_wl;
  cudaGetSymbolAddress((void**)&p_h,  g_h);
  cudaGetSymbolAddress((void**)&p_ah, g_Ah);
  cudaGetSymbolAddress((void**)&p_al, g_Al);
  cudaGetSymbolAddress((void**)&p_wh, g_Wth);
  cudaGetSymbolAddress((void**)&p_wl, g_Wtl);

  cudaFuncSetAttribute(k_mma, cudaFuncAttributeMaxDynamicSharedMemorySize, MMA_SMEM);

  const int TB=256;
  const int gN=(NN+TB-1)/TB;            // 196
  const int gE=(EE+TB-1)/TB;
  const int gW=(NN+7)/8;
  const int gM=NP/128;                  // 391
  const int gI=(CC*CC+CC+TB-1)/TB;      // init covers adj zeroing too

  // graph prep
  k_init<<<gI,TB>>>(out);
  k_deg<<<gE,TB>>>(dstp);
  k_scan1<<<gN,TB>>>();
  k_scan2<<<1,256>>>(gN);
  k_scan3p<<<gN,TB>>>();
  k_scatter<<<gE,TB>>>(srcp,dstp);
  k_wsplit3<<<(WTOT+TB-1)/TB,TB>>>(W1,W2,W3);

  // layer 1: F=128 -> 256 (hs fused into agg)
  k_agg<1,true><<<gW,TB>>>(x,p_ah,p_al,Wsm);
  k_mma<<<dim3(2,gM),256,MMA_SMEM>>>(p_ah,p_al,p_wh+WOFF1,p_wl+WOFF1,b1,p_h,128,256);

  // layer 2: 256 -> 256
  k_agg<2,false><<<gW,TB>>>(p_h,p_ah,p_al,Wsm);
  k_mma<<<dim3(2,gM),256,MMA_SMEM>>>(p_ah,p_al,p_wh+WOFF2,p_wl+WOFF2,b2,p_h,256,256);

  // layer 3: 256 -> 512
  k_agg<2,false><<<gW,TB>>>(p_h,p_ah,p_al,Wsm);
  k_mma<<<dim3(4,gM),256,MMA_SMEM>>>(p_ah,p_al,p_wh+WOFF3,p_wl+WOFF3,b3,p_h,256,512);

  // softmax S + hard cluster assignment
  k_softmax<<<gW,TB>>>(p_h, out+OFF_S);

  // score branch (score+segreduce+adj fused)
  k_degs<<<gN,TB>>>();
  k_score<<<gN,TB>>>(bs,out);

  // pooled features
  k_newx<<<CC,FF>>>(x,out);
}